// round 15
// baseline (speedup 1.0000x reference)
#include <cuda_runtime.h>
#include <cuda_bf16.h>
#include <cstdint>

#define BB 64
#define SS 512
#define EE 256
#define HH 512
#define FH 2048
#define NBLK 128
#define NT 256

// ---- recurrence smem byte offsets
#define WH 0                 // weight hi: 40 rows x 520 bf16 (pitch 1040B)
#define WL 41600
#define PH 83200             // state planes: 32 rows x 520 bf16 each
#define PHL 116480
#define PC 149760
#define PCL 183040
#define BIASB 216320         // 40 floats
#define RED 83200            // reduce scratch aliases PH (20480B)
#define SMEM_DYN 216480
#define PITCH 1040

// ---- u_gemm smem byte offsets (XH also aliased by OUT after mainloop)
#define UXH 0                // X hi: 64 rows x 528B
#define UXL 33792
#define UUH 67584            // U hi: 128 rows x 528B
#define UUL 135168
#define SMEM_UG 202752
#define UPITCH 528

__device__ __align__(16) __nv_bfloat16 g_hhi[BB * HH];
__device__ __align__(16) __nv_bfloat16 g_hlo[BB * HH];
__device__ __align__(16) __nv_bfloat16 g_chi[BB * HH];
__device__ __align__(16) __nv_bfloat16 g_clo[BB * HH];
__device__ float g_u[(size_t)SS * BB * FH];
__device__ unsigned g_leaf[8 * 64];   // 8 leaf counters, 256B apart (LTS spread)
__device__ unsigned g_root;           // monotonic; never reset (replay-safe)

// ---------------------------------------------------------------------------
__device__ __forceinline__ uint32_t smem_u32(const void* p) {
    uint32_t a;
    asm("{ .reg .u64 t; cvta.to.shared.u64 t, %1; cvt.u32.u64 %0, t; }"
        : "=r"(a) : "l"(p));
    return a;
}
__device__ __forceinline__ void cpasync16(uint32_t dst, const void* src) {
    asm volatile("cp.async.cg.shared.global [%0], [%1], 16;"
                 :: "r"(dst), "l"(src));
}
#define CP_COMMIT() asm volatile("cp.async.commit_group;")
#define CP_WAIT0()  asm volatile("cp.async.wait_group 0;")
__device__ __forceinline__ unsigned short f2bf(float x) {
    unsigned short r;
    asm("cvt.rn.bf16.f32 %0, %1;" : "=h"(r) : "f"(x));
    return r;
}
__device__ __forceinline__ float bf2f(unsigned short u) {
    return __uint_as_float(((unsigned)u) << 16);
}
__device__ __forceinline__ float tanha(float x) {
    float y;
    asm("tanh.approx.f32 %0, %1;" : "=f"(y) : "f"(x));
    return y;
}
__device__ __forceinline__ float sigm(float x) {
    return 0.5f * tanha(0.5f * x) + 0.5f;
}
#define LDM4(r, a) \
    asm volatile("ldmatrix.sync.aligned.m8n8.x4.shared.b16 {%0,%1,%2,%3},[%4];" \
        : "=r"((r)[0]), "=r"((r)[1]), "=r"((r)[2]), "=r"((r)[3]) : "r"(a))
#define LDM2(r0, r1, a) \
    asm volatile("ldmatrix.sync.aligned.m8n8.x2.shared.b16 {%0,%1},[%2];" \
        : "=r"(r0), "=r"(r1) : "r"(a))
#define MMA(d, a, b0, b1) \
    asm volatile("mma.sync.aligned.m16n8k16.row.col.f32.bf16.bf16.f32 " \
        "{%0,%1,%2,%3},{%4,%5,%6,%7},{%8,%9},{%0,%1,%2,%3};" \
        : "+f"((d)[0]), "+f"((d)[1]), "+f"((d)[2]), "+f"((d)[3]) \
        : "r"((a)[0]), "r"((a)[1]), "r"((a)[2]), "r"((a)[3]), "r"(b0), "r"(b1))

// Hierarchical monotonic grid barrier. Leaf arrivals (16 blocks each) spread
// over 8 L2 slices; root sees only 8 arrivals. acq_rel atomics carry the
// release->acquire chain: block stores -> leaf -> root -> waiter.
__device__ __forceinline__ void gridbar() {
    __syncthreads();
    if (threadIdx.x == 0) {
        unsigned* leaf = &g_leaf[(blockIdx.x & 7) * 64];
        unsigned my;
        asm volatile("atom.acq_rel.gpu.global.add.u32 %0, [%1], %2;"
                     : "=r"(my) : "l"(leaf), "r"(1u) : "memory");
        unsigned round = my >> 4;                  // 16 blocks per leaf
        if ((my & 15u) == 15u) {
            unsigned tmp;
            asm volatile("atom.acq_rel.gpu.global.add.u32 %0, [%1], %2;"
                         : "=r"(tmp) : "l"(&g_root), "r"(1u) : "memory");
        }
        unsigned target = (round + 1u) * 8u;
        unsigned v;
        do {
            asm volatile("ld.acquire.gpu.global.u32 %0, [%1];"
                         : "=r"(v) : "l"(&g_root) : "memory");
        } while (v < target);
    }
    __syncthreads();
}

// ---------------------------------------------------------------------------
// u_all GEMM via split-bf16 mma.sync (3-pass). Block: 64 batches at fixed s
// x 128 n-cols, K=256 smem-resident. 8 warps = 2 m-halves x 4 n-quarters.
// ---------------------------------------------------------------------------
__global__ __launch_bounds__(256) void u_gemm_mma(
    const float* __restrict__ X, const float* __restrict__ U,
    const float* __restrict__ Ub)
{
    extern __shared__ char smc[];
    const uint32_t base = smem_u32(smc);
    const int t = threadIdx.x, wid = t >> 5, lane = t & 31;
    const int s = blockIdx.x, n0 = blockIdx.y * 128;
    const int mw = wid & 1, nw = wid >> 1;

    // load + split-convert X (64 x 256 fp32 -> hi/lo bf16 planes)
#pragma unroll
    for (int q = 0; q < 16; q++) {
        int i = t + 256 * q;
        int row = i >> 6, k4 = i & 63;
        float4 v = __ldg((const float4*)(X + ((size_t)row * SS + s) * EE) + k4);
        unsigned short h0 = f2bf(v.x), h1 = f2bf(v.y),
                       h2 = f2bf(v.z), h3 = f2bf(v.w);
        unsigned short l0 = f2bf(v.x - bf2f(h0)), l1 = f2bf(v.y - bf2f(h1)),
                       l2 = f2bf(v.z - bf2f(h2)), l3 = f2bf(v.w - bf2f(h3));
        uint2 hv = make_uint2((uint32_t)h0 | ((uint32_t)h1 << 16),
                              (uint32_t)h2 | ((uint32_t)h3 << 16));
        uint2 lv = make_uint2((uint32_t)l0 | ((uint32_t)l1 << 16),
                              (uint32_t)l2 | ((uint32_t)l3 << 16));
        *(uint2*)(smc + UXH + row * UPITCH + k4 * 8) = hv;
        *(uint2*)(smc + UXL + row * UPITCH + k4 * 8) = lv;
    }
    // load + split-convert U slice (128 x 256)
#pragma unroll
    for (int q = 0; q < 32; q++) {
        int i = t + 256 * q;
        int row = i >> 6, k4 = i & 63;
        float4 v = __ldg((const float4*)(U + (size_t)(n0 + row) * EE) + k4);
        unsigned short h0 = f2bf(v.x), h1 = f2bf(v.y),
                       h2 = f2bf(v.z), h3 = f2bf(v.w);
        unsigned short l0 = f2bf(v.x - bf2f(h0)), l1 = f2bf(v.y - bf2f(h1)),
                       l2 = f2bf(v.z - bf2f(h2)), l3 = f2bf(v.w - bf2f(h3));
        uint2 hv = make_uint2((uint32_t)h0 | ((uint32_t)h1 << 16),
                              (uint32_t)h2 | ((uint32_t)h3 << 16));
        uint2 lv = make_uint2((uint32_t)l0 | ((uint32_t)l1 << 16),
                              (uint32_t)l2 | ((uint32_t)l3 << 16));
        *(uint2*)(smc + UUH + row * UPITCH + k4 * 8) = hv;
        *(uint2*)(smc + UUL + row * UPITCH + k4 * 8) = lv;
    }
    __syncthreads();

    float acc[2][4][4];
#pragma unroll
    for (int mf = 0; mf < 2; mf++)
#pragma unroll
        for (int nf = 0; nf < 4; nf++)
#pragma unroll
            for (int r = 0; r < 4; r++) acc[mf][nf][r] = 0.f;

    const int l = lane & 15;
#pragma unroll
    for (int kt = 0; kt < 16; kt++) {
        uint32_t ah[2][4], al[2][4];
#pragma unroll
        for (int mf = 0; mf < 2; mf++) {
            uint32_t ad = base + UXH + (mw * 32 + mf * 16 + l) * UPITCH +
                          kt * 32 + (lane >> 4) * 16;
            LDM4(ah[mf], ad);
            LDM4(al[mf], ad + (UXL - UXH));
        }
        uint32_t bh_[4][2], bl_[4][2];
#pragma unroll
        for (int nf = 0; nf < 4; nf++) {
            uint32_t bd = base + UUH + (nw * 32 + nf * 8 + (l & 7)) * UPITCH +
                          kt * 32 + ((l >> 3) & 1) * 16;
            LDM2(bh_[nf][0], bh_[nf][1], bd);
            LDM2(bl_[nf][0], bl_[nf][1], bd + (UUL - UUH));
        }
#pragma unroll
        for (int mf = 0; mf < 2; mf++)
#pragma unroll
            for (int nf = 0; nf < 4; nf++) {
                MMA(acc[mf][nf], ah[mf], bh_[nf][0], bh_[nf][1]);
                MMA(acc[mf][nf], ah[mf], bl_[nf][0], bl_[nf][1]);
                MMA(acc[mf][nf], al[mf], bh_[nf][0], bh_[nf][1]);
            }
    }
    __syncthreads();   // OUT aliases XH region below

    // scatter frags to OUT (64 rows x 128 cols fp32, pitch 130 floats)
    float* OUT = (float*)smc;
#pragma unroll
    for (int mf = 0; mf < 2; mf++)
#pragma unroll
        for (int nf = 0; nf < 4; nf++)
#pragma unroll
            for (int r = 0; r < 4; r++) {
                int row = mw * 32 + mf * 16 + (lane >> 2) + (r >> 1) * 8;
                int col = nw * 32 + nf * 8 + (lane & 3) * 2 + (r & 1);
                OUT[row * 130 + col] = acc[mf][nf][r];
            }
    __syncthreads();

    // coalesced copy + bias
#pragma unroll
    for (int q = 0; q < 16; q++) {
        int i = t + 256 * q;
        int row = i >> 6, c2 = i & 63;
        float2 v = *(float2*)(OUT + row * 130 + c2 * 2);
        int n = n0 + c2 * 2;
        v.x += __ldg(Ub + n);
        v.y += __ldg(Ub + n + 1);
        *(float2*)(g_u + ((size_t)s * BB + row) * FH + n) = v;
    }
}

// ---------------------------------------------------------------------------
// Persistent mma.sync recurrence (R14 structure, hierarchical barrier).
// 128 blocks = 64 j-tiles x 2 batch-halves. 8 warps = 2 m-tiles x 4 k-quarters.
// ---------------------------------------------------------------------------
__global__ __launch_bounds__(NT, 1) void lstm_mma(
    const float* __restrict__ Wall, const float* __restrict__ Wall_b,
    const float* __restrict__ Wd, const float* __restrict__ Wd_b,
    const float* __restrict__ ts, float* __restrict__ out, int write_tail)
{
    extern __shared__ char smc[];
    const uint32_t base = smem_u32(smc);
    const int t = threadIdx.x, wid = t >> 5, lane = t & 31;
    const int jt = blockIdx.x >> 1, bh = blockIdx.x & 1;
    const int j0 = jt * 8;
    const int mw = wid & 1, kq = wid >> 1;

    // one-time: split weights into smem (40 rows x 512, pitch 1040B)
#pragma unroll 4
    for (int it = 0; it < 80; it++) {
        int i = t + NT * it;
        int r = i >> 9, k = i & 511;
        float w = (r < 32) ? Wall[(size_t)((r >> 3) * HH + j0 + (r & 7)) * HH + k]
                           : Wd[(size_t)(j0 + (r & 7)) * HH + k];
        unsigned short hi = f2bf(w);
        unsigned short lo = f2bf(w - bf2f(hi));
        *(unsigned short*)(smc + WH + r * PITCH + k * 2) = hi;
        *(unsigned short*)(smc + WL + r * PITCH + k * 2) = lo;
    }
    if (t < 40) {
        ((float*)(smc + BIASB))[t] =
            (t < 32) ? Wall_b[(t >> 3) * HH + j0 + (t & 7)]
                     : Wd_b[j0 + (t & 7)];
    }
    __syncthreads();

    // persistent B-hi fragments: 5 slots x 8 k-tiles x 2 regs
    uint32_t bhi[5][8][2];
    {
        int l = lane & 15;
        int brow = l & 7, bk = (l >> 3) & 1;
#pragma unroll
        for (int ns = 0; ns < 5; ns++)
#pragma unroll
            for (int kt = 0; kt < 8; kt++) {
                uint32_t a = base + WH + (ns * 8 + brow) * PITCH +
                             (kq * 128 + kt * 16) * 2 + bk * 16;
                LDM2(bhi[ns][kt][0], bhi[ns][kt][1], a);
            }
    }
    const uint32_t bloAddr0 = base + WL + ((lane & 15) & 7) * PITCH +
                              (((lane & 15) >> 3) & 1) * 16 + kq * 256;
    const uint32_t aoff = (mw * 16 + (lane & 15)) * PITCH + (lane >> 4) * 16 +
                          kq * 256;

    // epilogue identity
    const int eb = t >> 3, ejl = t & 7;
    const int bg = bh * 32 + eb, ej = j0 + ejl;
    const float zb0 = ((float*)(smc + BIASB))[ejl];
    const float zb1 = ((float*)(smc + BIASB))[8 + ejl];
    const float zb2 = ((float*)(smc + BIASB))[16 + ejl];
    const float zb3 = ((float*)(smc + BIASB))[24 + ejl];
    const float zb4 = ((float*)(smc + BIASB))[32 + ejl];
    float ccar = 0.f;

    for (int s = 0; s < SS; s++) {
        // epilogue operand prefetch
        const float* ur = g_u + ((size_t)s * BB + bg) * FH + ej;
        float u0 = __ldcs(ur);
        float u1 = __ldcs(ur + HH);
        float u2 = __ldcs(ur + 2 * HH);
        float u3 = __ldcs(ur + 3 * HH);
        float tsv = __ldg(ts + (size_t)bg * SS + s);

        // stage 4 state planes (32 rows x 512 bf16 each); s==0 zero-fill
        if (s == 0) {
#pragma unroll
            for (int q = 0; q < 33; q++) {
                int i = t + NT * q;
                if (i < 8320)
                    ((uint4*)(smc + PH))[i] = make_uint4(0, 0, 0, 0);
            }
        } else {
#pragma unroll
            for (int q = 0; q < 32; q++) {
                int i = t + NT * (q & 7);
                int row = i >> 6, seg = i & 63;
                int p = q >> 3;
                const __nv_bfloat16* gp =
                    (p == 0) ? g_hhi : (p == 1) ? g_hlo : (p == 2) ? g_chi : g_clo;
                cpasync16(base + PH + p * 33280 + row * PITCH + seg * 16,
                          gp + (size_t)(bh * 32 + row) * HH + seg * 8);
            }
            CP_COMMIT();
            CP_WAIT0();
        }
        __syncthreads();

        float acc[5][4];
#pragma unroll
        for (int ns = 0; ns < 5; ns++)
#pragma unroll
            for (int r = 0; r < 4; r++) acc[ns][r] = 0.f;

#pragma unroll
        for (int kt = 0; kt < 8; kt++) {
            uint32_t kb = kt * 32;
            uint32_t ahh[4], ahl[4], ach[4], acl[4];
            LDM4(ahh, base + PH + aoff + kb);
            LDM4(ahl, base + PHL + aoff + kb);
            LDM4(ach, base + PC + aoff + kb);
            LDM4(acl, base + PCL + aoff + kb);
            uint32_t bl[5][2];
#pragma unroll
            for (int ns = 0; ns < 5; ns++)
                LDM2(bl[ns][0], bl[ns][1], bloAddr0 + ns * 8 * PITCH + kb);
#pragma unroll
            for (int ns = 0; ns < 4; ns++) {
                MMA(acc[ns], ahh, bhi[ns][kt][0], bhi[ns][kt][1]);
                MMA(acc[ns], ahh, bl[ns][0], bl[ns][1]);
                MMA(acc[ns], ahl, bhi[ns][kt][0], bhi[ns][kt][1]);
            }
            MMA(acc[4], ach, bhi[4][kt][0], bhi[4][kt][1]);
            MMA(acc[4], ach, bl[4][0], bl[4][1]);
            MMA(acc[4], acl, bhi[4][kt][0], bhi[4][kt][1]);
        }
        __syncthreads();  // reduce scratch aliases PH plane

        // scatter partials: R[((kq*5+g)*32 + row)*8 + jl]
        {
            float* R = (float*)(smc + RED);
#pragma unroll
            for (int ns = 0; ns < 5; ns++)
#pragma unroll
                for (int r = 0; r < 4; r++) {
                    int row = mw * 16 + (lane >> 2) + (r >> 1) * 8;
                    int jl = (lane & 3) * 2 + (r & 1);
                    R[((kq * 5 + ns) * 32 + row) * 8 + jl] = acc[ns][r];
                }
        }
        __syncthreads();

        // gather + gate epilogue (each thread: one (batch, j))
        {
            const float* R = (float*)(smc + RED);
            float s0 = 0, s1 = 0, s2 = 0, s3 = 0, s4 = 0;
#pragma unroll
            for (int k2 = 0; k2 < 4; k2++) {
                const float* Rq = R + (k2 * 5 * 32 + eb) * 8 + ejl;
                s0 += Rq[0];
                s1 += Rq[32 * 8];
                s2 += Rq[64 * 8];
                s3 += Rq[96 * 8];
                s4 += Rq[128 * 8];
            }
            float pf = s0 + zb0 + u0;
            float pi = s1 + zb1 + u1;
            float po = s2 + zb2 + u2;
            float pg = s3 + zb3 + u3;
            float dd = s4 + zb4;

            float cs1 = tanha(dd);
            float cadj = (ccar - cs1) + cs1 * tsv;
            float cnew = sigm(pf) * cadj + sigm(pi) * sigm(pg);
            float hnew = sigm(po) * tanha(cnew);
            ccar = cnew;

            out[((size_t)bg * SS + s) * HH + ej] = hnew;

            unsigned short hh = f2bf(hnew);
            unsigned short hl = f2bf(hnew - bf2f(hh));
            unsigned short ch = f2bf(cnew);
            unsigned short cl = f2bf(cnew - bf2f(ch));
            size_t po_ = (size_t)bg * HH + ej;
            g_hhi[po_] = *(__nv_bfloat16*)&hh;
            g_hlo[po_] = *(__nv_bfloat16*)&hl;
            g_chi[po_] = *(__nv_bfloat16*)&ch;
            g_clo[po_] = *(__nv_bfloat16*)&cl;

            if (s == SS - 1 && write_tail) {
                out[(size_t)BB * SS * HH + po_] = hnew;
                out[(size_t)BB * SS * HH + (size_t)BB * HH + po_] = cnew;
            }
        }

        if (s != SS - 1) gridbar();
    }
}

// ---------------------------------------------------------------------------
extern "C" void kernel_launch(void* const* d_in, const int* in_sizes, int n_in,
                              void* d_out, int out_size) {
    const float* X      = (const float*)d_in[0];
    const float* ts     = (const float*)d_in[1];
    const float* Wall   = (const float*)d_in[2];
    const float* Wall_b = (const float*)d_in[3];
    const float* U      = (const float*)d_in[4];
    const float* Ub     = (const float*)d_in[5];
    const float* Wd     = (const float*)d_in[6];
    const float* Wdb    = (const float*)d_in[7];
    float* out = (float*)d_out;

    cudaFuncSetAttribute(u_gemm_mma, cudaFuncAttributeMaxDynamicSharedMemorySize,
                         SMEM_UG);
    cudaFuncSetAttribute(lstm_mma, cudaFuncAttributeMaxDynamicSharedMemorySize,
                         SMEM_DYN);

    dim3 gu(SS, 16);
    u_gemm_mma<<<gu, 256, SMEM_UG>>>(X, U, Ub);

    long long need = (long long)BB * SS * HH + 2LL * BB * HH;
    int write_tail = ((long long)out_size >= need) ? 1 : 0;
    lstm_mma<<<NBLK, NT, SMEM_DYN>>>(Wall, Wall_b, Wd, Wdb, ts, out, write_tail);
}

// round 16
// speedup vs baseline: 1.1331x; 1.1331x over previous
#include <cuda_runtime.h>
#include <cuda_bf16.h>
#include <cstdint>

#define BB 64
#define SS 512
#define EE 256
#define HH 512
#define FH 2048
#define NBLK 128
#define NT 256

// ---- recurrence smem byte offsets
#define WH 0                 // weight hi: 40 rows x 520 bf16 (pitch 1040B)
#define WL 41600
#define PH 83200             // state planes: 32 rows x 520 bf16 each
#define PHL 116480
#define PC 149760
#define PCL 183040
#define BIASB 216320         // 40 floats
#define RED 83200            // reduce scratch aliases PH (20480B)
#define SMEM_DYN 216480
#define PITCH 1040

// ---- u_gemm smem byte offsets (XH also aliased by OUT after mainloop)
#define UXH 0                // X hi: 64 rows x 528B
#define UXL 33792
#define UUH 67584            // U hi: 128 rows x 528B
#define UUL 135168
#define SMEM_UG 202752
#define UPITCH 528

__device__ __align__(16) __nv_bfloat16 g_hhi[BB * HH];
__device__ __align__(16) __nv_bfloat16 g_hlo[BB * HH];
__device__ __align__(16) __nv_bfloat16 g_chi[BB * HH];
__device__ __align__(16) __nv_bfloat16 g_clo[BB * HH];
__device__ float g_u[(size_t)SS * BB * FH];
// Two independent per-half barrier counters, 256B apart (different L2 lines).
// Monotonic, never reset (graph-replay safe).
__device__ unsigned g_cnt2[2 * 64];

// ---------------------------------------------------------------------------
__device__ __forceinline__ uint32_t smem_u32(const void* p) {
    uint32_t a;
    asm("{ .reg .u64 t; cvta.to.shared.u64 t, %1; cvt.u32.u64 %0, t; }"
        : "=r"(a) : "l"(p));
    return a;
}
__device__ __forceinline__ void cpasync16(uint32_t dst, const void* src) {
    asm volatile("cp.async.cg.shared.global [%0], [%1], 16;"
                 :: "r"(dst), "l"(src));
}
#define CP_COMMIT() asm volatile("cp.async.commit_group;")
#define CP_WAIT0()  asm volatile("cp.async.wait_group 0;")
__device__ __forceinline__ unsigned short f2bf(float x) {
    unsigned short r;
    asm("cvt.rn.bf16.f32 %0, %1;" : "=h"(r) : "f"(x));
    return r;
}
__device__ __forceinline__ float bf2f(unsigned short u) {
    return __uint_as_float(((unsigned)u) << 16);
}
__device__ __forceinline__ float tanha(float x) {
    float y;
    asm("tanh.approx.f32 %0, %1;" : "=f"(y) : "f"(x));
    return y;
}
__device__ __forceinline__ float sigm(float x) {
    return 0.5f * tanha(0.5f * x) + 0.5f;
}
#define LDM4(r, a) \
    asm volatile("ldmatrix.sync.aligned.m8n8.x4.shared.b16 {%0,%1,%2,%3},[%4];" \
        : "=r"((r)[0]), "=r"((r)[1]), "=r"((r)[2]), "=r"((r)[3]) : "r"(a))
#define LDM2(r0, r1, a) \
    asm volatile("ldmatrix.sync.aligned.m8n8.x2.shared.b16 {%0,%1},[%2];" \
        : "=r"(r0), "=r"(r1) : "r"(a))
#define MMA(d, a, b0, b1) \
    asm volatile("mma.sync.aligned.m16n8k16.row.col.f32.bf16.bf16.f32 " \
        "{%0,%1,%2,%3},{%4,%5,%6,%7},{%8,%9},{%0,%1,%2,%3};" \
        : "+f"((d)[0]), "+f"((d)[1]), "+f"((d)[2]), "+f"((d)[3]) \
        : "r"((a)[0]), "r"((a)[1]), "r"((a)[2]), "r"((a)[3]), "r"(b0), "r"(b1))

// Per-batch-half flat monotonic grid barrier: 64 arrivals each, independent
// counters on separate L2 lines. Same proven structure as the R14 barrier.
__device__ __forceinline__ void gridbar_half(int bh) {
    __syncthreads();
    if (threadIdx.x == 0) {
        __threadfence();
        unsigned* cnt = &g_cnt2[bh * 64];
        unsigned my = atomicAdd(cnt, 1u);
        unsigned target = (my / 64u + 1u) * 64u;
        unsigned v;
        do {
            asm volatile("ld.acquire.gpu.global.u32 %0, [%1];"
                         : "=r"(v) : "l"(cnt) : "memory");
        } while (v < target);
    }
    __syncthreads();
}

// ---------------------------------------------------------------------------
// u_all GEMM via split-bf16 mma.sync (3-pass). Block: 64 batches at fixed s
// x 128 n-cols, K=256 smem-resident. 8 warps = 2 m-halves x 4 n-quarters.
// ---------------------------------------------------------------------------
__global__ __launch_bounds__(256) void u_gemm_mma(
    const float* __restrict__ X, const float* __restrict__ U,
    const float* __restrict__ Ub)
{
    extern __shared__ char smc[];
    const uint32_t base = smem_u32(smc);
    const int t = threadIdx.x, wid = t >> 5, lane = t & 31;
    const int s = blockIdx.x, n0 = blockIdx.y * 128;
    const int mw = wid & 1, nw = wid >> 1;

    // load + split-convert X (64 x 256 fp32 -> hi/lo bf16 planes)
#pragma unroll
    for (int q = 0; q < 16; q++) {
        int i = t + 256 * q;
        int row = i >> 6, k4 = i & 63;
        float4 v = __ldg((const float4*)(X + ((size_t)row * SS + s) * EE) + k4);
        unsigned short h0 = f2bf(v.x), h1 = f2bf(v.y),
                       h2 = f2bf(v.z), h3 = f2bf(v.w);
        unsigned short l0 = f2bf(v.x - bf2f(h0)), l1 = f2bf(v.y - bf2f(h1)),
                       l2 = f2bf(v.z - bf2f(h2)), l3 = f2bf(v.w - bf2f(h3));
        uint2 hv = make_uint2((uint32_t)h0 | ((uint32_t)h1 << 16),
                              (uint32_t)h2 | ((uint32_t)h3 << 16));
        uint2 lv = make_uint2((uint32_t)l0 | ((uint32_t)l1 << 16),
                              (uint32_t)l2 | ((uint32_t)l3 << 16));
        *(uint2*)(smc + UXH + row * UPITCH + k4 * 8) = hv;
        *(uint2*)(smc + UXL + row * UPITCH + k4 * 8) = lv;
    }
    // load + split-convert U slice (128 x 256)
#pragma unroll
    for (int q = 0; q < 32; q++) {
        int i = t + 256 * q;
        int row = i >> 6, k4 = i & 63;
        float4 v = __ldg((const float4*)(U + (size_t)(n0 + row) * EE) + k4);
        unsigned short h0 = f2bf(v.x), h1 = f2bf(v.y),
                       h2 = f2bf(v.z), h3 = f2bf(v.w);
        unsigned short l0 = f2bf(v.x - bf2f(h0)), l1 = f2bf(v.y - bf2f(h1)),
                       l2 = f2bf(v.z - bf2f(h2)), l3 = f2bf(v.w - bf2f(h3));
        uint2 hv = make_uint2((uint32_t)h0 | ((uint32_t)h1 << 16),
                              (uint32_t)h2 | ((uint32_t)h3 << 16));
        uint2 lv = make_uint2((uint32_t)l0 | ((uint32_t)l1 << 16),
                              (uint32_t)l2 | ((uint32_t)l3 << 16));
        *(uint2*)(smc + UUH + row * UPITCH + k4 * 8) = hv;
        *(uint2*)(smc + UUL + row * UPITCH + k4 * 8) = lv;
    }
    __syncthreads();

    float acc[2][4][4];
#pragma unroll
    for (int mf = 0; mf < 2; mf++)
#pragma unroll
        for (int nf = 0; nf < 4; nf++)
#pragma unroll
            for (int r = 0; r < 4; r++) acc[mf][nf][r] = 0.f;

    const int l = lane & 15;
#pragma unroll
    for (int kt = 0; kt < 16; kt++) {
        uint32_t ah[2][4], al[2][4];
#pragma unroll
        for (int mf = 0; mf < 2; mf++) {
            uint32_t ad = base + UXH + (mw * 32 + mf * 16 + l) * UPITCH +
                          kt * 32 + (lane >> 4) * 16;
            LDM4(ah[mf], ad);
            LDM4(al[mf], ad + (UXL - UXH));
        }
        uint32_t bh_[4][2], bl_[4][2];
#pragma unroll
        for (int nf = 0; nf < 4; nf++) {
            uint32_t bd = base + UUH + (nw * 32 + nf * 8 + (l & 7)) * UPITCH +
                          kt * 32 + ((l >> 3) & 1) * 16;
            LDM2(bh_[nf][0], bh_[nf][1], bd);
            LDM2(bl_[nf][0], bl_[nf][1], bd + (UUL - UUH));
        }
#pragma unroll
        for (int mf = 0; mf < 2; mf++)
#pragma unroll
            for (int nf = 0; nf < 4; nf++) {
                MMA(acc[mf][nf], ah[mf], bh_[nf][0], bh_[nf][1]);
                MMA(acc[mf][nf], ah[mf], bl_[nf][0], bl_[nf][1]);
                MMA(acc[mf][nf], al[mf], bh_[nf][0], bh_[nf][1]);
            }
    }
    __syncthreads();   // OUT aliases XH region below

    // scatter frags to OUT (64 rows x 128 cols fp32, pitch 130 floats)
    float* OUT = (float*)smc;
#pragma unroll
    for (int mf = 0; mf < 2; mf++)
#pragma unroll
        for (int nf = 0; nf < 4; nf++)
#pragma unroll
            for (int r = 0; r < 4; r++) {
                int row = mw * 32 + mf * 16 + (lane >> 2) + (r >> 1) * 8;
                int col = nw * 32 + nf * 8 + (lane & 3) * 2 + (r & 1);
                OUT[row * 130 + col] = acc[mf][nf][r];
            }
    __syncthreads();

    // coalesced copy + bias
#pragma unroll
    for (int q = 0; q < 16; q++) {
        int i = t + 256 * q;
        int row = i >> 6, c2 = i & 63;
        float2 v = *(float2*)(OUT + row * 130 + c2 * 2);
        int n = n0 + c2 * 2;
        v.x += __ldg(Ub + n);
        v.y += __ldg(Ub + n + 1);
        *(float2*)(g_u + ((size_t)s * BB + row) * FH + n) = v;
    }
}

// ---------------------------------------------------------------------------
// Persistent mma.sync recurrence (R14 structure; per-half barrier).
// 128 blocks = 64 j-tiles x 2 batch-halves. 8 warps = 2 m-tiles x 4 k-quarters.
// ---------------------------------------------------------------------------
__global__ __launch_bounds__(NT, 1) void lstm_mma(
    const float* __restrict__ Wall, const float* __restrict__ Wall_b,
    const float* __restrict__ Wd, const float* __restrict__ Wd_b,
    const float* __restrict__ ts, float* __restrict__ out, int write_tail)
{
    extern __shared__ char smc[];
    const uint32_t base = smem_u32(smc);
    const int t = threadIdx.x, wid = t >> 5, lane = t & 31;
    const int jt = blockIdx.x >> 1, bh = blockIdx.x & 1;
    const int j0 = jt * 8;
    const int mw = wid & 1, kq = wid >> 1;

    // one-time: split weights into smem (40 rows x 512, pitch 1040B)
#pragma unroll 4
    for (int it = 0; it < 80; it++) {
        int i = t + NT * it;
        int r = i >> 9, k = i & 511;
        float w = (r < 32) ? Wall[(size_t)((r >> 3) * HH + j0 + (r & 7)) * HH + k]
                           : Wd[(size_t)(j0 + (r & 7)) * HH + k];
        unsigned short hi = f2bf(w);
        unsigned short lo = f2bf(w - bf2f(hi));
        *(unsigned short*)(smc + WH + r * PITCH + k * 2) = hi;
        *(unsigned short*)(smc + WL + r * PITCH + k * 2) = lo;
    }
    if (t < 40) {
        ((float*)(smc + BIASB))[t] =
            (t < 32) ? Wall_b[(t >> 3) * HH + j0 + (t & 7)]
                     : Wd_b[j0 + (t & 7)];
    }
    __syncthreads();

    // persistent B-hi fragments: 5 slots x 8 k-tiles x 2 regs
    uint32_t bhi[5][8][2];
    {
        int l = lane & 15;
        int brow = l & 7, bk = (l >> 3) & 1;
#pragma unroll
        for (int ns = 0; ns < 5; ns++)
#pragma unroll
            for (int kt = 0; kt < 8; kt++) {
                uint32_t a = base + WH + (ns * 8 + brow) * PITCH +
                             (kq * 128 + kt * 16) * 2 + bk * 16;
                LDM2(bhi[ns][kt][0], bhi[ns][kt][1], a);
            }
    }
    const uint32_t bloAddr0 = base + WL + ((lane & 15) & 7) * PITCH +
                              (((lane & 15) >> 3) & 1) * 16 + kq * 256;
    const uint32_t aoff = (mw * 16 + (lane & 15)) * PITCH + (lane >> 4) * 16 +
                          kq * 256;

    // epilogue identity
    const int eb = t >> 3, ejl = t & 7;
    const int bg = bh * 32 + eb, ej = j0 + ejl;
    const float zb0 = ((float*)(smc + BIASB))[ejl];
    const float zb1 = ((float*)(smc + BIASB))[8 + ejl];
    const float zb2 = ((float*)(smc + BIASB))[16 + ejl];
    const float zb3 = ((float*)(smc + BIASB))[24 + ejl];
    const float zb4 = ((float*)(smc + BIASB))[32 + ejl];
    float ccar = 0.f;

    for (int s = 0; s < SS; s++) {
        // epilogue operand prefetch
        const float* ur = g_u + ((size_t)s * BB + bg) * FH + ej;
        float u0 = __ldcs(ur);
        float u1 = __ldcs(ur + HH);
        float u2 = __ldcs(ur + 2 * HH);
        float u3 = __ldcs(ur + 3 * HH);
        float tsv = __ldg(ts + (size_t)bg * SS + s);

        // stage 4 state planes (32 rows x 512 bf16 each); s==0 zero-fill
        if (s == 0) {
#pragma unroll
            for (int q = 0; q < 33; q++) {
                int i = t + NT * q;
                if (i < 8320)
                    ((uint4*)(smc + PH))[i] = make_uint4(0, 0, 0, 0);
            }
        } else {
#pragma unroll
            for (int q = 0; q < 32; q++) {
                int i = t + NT * (q & 7);
                int row = i >> 6, seg = i & 63;
                int p = q >> 3;
                const __nv_bfloat16* gp =
                    (p == 0) ? g_hhi : (p == 1) ? g_hlo : (p == 2) ? g_chi : g_clo;
                cpasync16(base + PH + p * 33280 + row * PITCH + seg * 16,
                          gp + (size_t)(bh * 32 + row) * HH + seg * 8);
            }
            CP_COMMIT();
            CP_WAIT0();
        }
        __syncthreads();

        float acc[5][4];
#pragma unroll
        for (int ns = 0; ns < 5; ns++)
#pragma unroll
            for (int r = 0; r < 4; r++) acc[ns][r] = 0.f;

#pragma unroll
        for (int kt = 0; kt < 8; kt++) {
            uint32_t kb = kt * 32;
            uint32_t ahh[4], ahl[4], ach[4], acl[4];
            LDM4(ahh, base + PH + aoff + kb);
            LDM4(ahl, base + PHL + aoff + kb);
            LDM4(ach, base + PC + aoff + kb);
            LDM4(acl, base + PCL + aoff + kb);
            uint32_t bl[5][2];
#pragma unroll
            for (int ns = 0; ns < 5; ns++)
                LDM2(bl[ns][0], bl[ns][1], bloAddr0 + ns * 8 * PITCH + kb);
#pragma unroll
            for (int ns = 0; ns < 4; ns++) {
                MMA(acc[ns], ahh, bhi[ns][kt][0], bhi[ns][kt][1]);
                MMA(acc[ns], ahh, bl[ns][0], bl[ns][1]);
                MMA(acc[ns], ahl, bhi[ns][kt][0], bhi[ns][kt][1]);
            }
            MMA(acc[4], ach, bhi[4][kt][0], bhi[4][kt][1]);
            MMA(acc[4], ach, bl[4][0], bl[4][1]);
            MMA(acc[4], acl, bhi[4][kt][0], bhi[4][kt][1]);
        }
        __syncthreads();  // reduce scratch aliases PH plane

        // scatter partials: R[((kq*5+g)*32 + row)*8 + jl]
        {
            float* R = (float*)(smc + RED);
#pragma unroll
            for (int ns = 0; ns < 5; ns++)
#pragma unroll
                for (int r = 0; r < 4; r++) {
                    int row = mw * 16 + (lane >> 2) + (r >> 1) * 8;
                    int jl = (lane & 3) * 2 + (r & 1);
                    R[((kq * 5 + ns) * 32 + row) * 8 + jl] = acc[ns][r];
                }
        }
        __syncthreads();

        // gather + gate epilogue (each thread: one (batch, j))
        {
            const float* R = (float*)(smc + RED);
            float s0 = 0, s1 = 0, s2 = 0, s3 = 0, s4 = 0;
#pragma unroll
            for (int k2 = 0; k2 < 4; k2++) {
                const float* Rq = R + (k2 * 5 * 32 + eb) * 8 + ejl;
                s0 += Rq[0];
                s1 += Rq[32 * 8];
                s2 += Rq[64 * 8];
                s3 += Rq[96 * 8];
                s4 += Rq[128 * 8];
            }
            float pf = s0 + zb0 + u0;
            float pi = s1 + zb1 + u1;
            float po = s2 + zb2 + u2;
            float pg = s3 + zb3 + u3;
            float dd = s4 + zb4;

            float cs1 = tanha(dd);
            float cadj = (ccar - cs1) + cs1 * tsv;
            float cnew = sigm(pf) * cadj + sigm(pi) * sigm(pg);
            float hnew = sigm(po) * tanha(cnew);
            ccar = cnew;

            // state planes FIRST (next step's critical data), then out
            unsigned short hh = f2bf(hnew);
            unsigned short hl = f2bf(hnew - bf2f(hh));
            unsigned short ch = f2bf(cnew);
            unsigned short cl = f2bf(cnew - bf2f(ch));
            size_t po_ = (size_t)bg * HH + ej;
            g_hhi[po_] = *(__nv_bfloat16*)&hh;
            g_hlo[po_] = *(__nv_bfloat16*)&hl;
            g_chi[po_] = *(__nv_bfloat16*)&ch;
            g_clo[po_] = *(__nv_bfloat16*)&cl;

            out[((size_t)bg * SS + s) * HH + ej] = hnew;

            if (s == SS - 1 && write_tail) {
                out[(size_t)BB * SS * HH + po_] = hnew;
                out[(size_t)BB * SS * HH + (size_t)BB * HH + po_] = cnew;
            }
        }

        if (s != SS - 1) gridbar_half(bh);
    }
}

// ---------------------------------------------------------------------------
extern "C" void kernel_launch(void* const* d_in, const int* in_sizes, int n_in,
                              void* d_out, int out_size) {
    const float* X      = (const float*)d_in[0];
    const float* ts     = (const float*)d_in[1];
    const float* Wall   = (const float*)d_in[2];
    const float* Wall_b = (const float*)d_in[3];
    const float* U      = (const float*)d_in[4];
    const float* Ub     = (const float*)d_in[5];
    const float* Wd     = (const float*)d_in[6];
    const float* Wdb    = (const float*)d_in[7];
    float* out = (float*)d_out;

    cudaFuncSetAttribute(u_gemm_mma, cudaFuncAttributeMaxDynamicSharedMemorySize,
                         SMEM_UG);
    cudaFuncSetAttribute(lstm_mma, cudaFuncAttributeMaxDynamicSharedMemorySize,
                         SMEM_DYN);

    dim3 gu(SS, 16);
    u_gemm_mma<<<gu, 256, SMEM_UG>>>(X, U, Ub);

    long long need = (long long)BB * SS * HH + 2LL * BB * HH;
    int write_tail = ((long long)out_size >= need) ? 1 : 0;
    lstm_mma<<<NBLK, NT, SMEM_DYN>>>(Wall, Wall_b, Wd, Wdb, ts, out, write_tail);
}

// round 17
// speedup vs baseline: 1.1769x; 1.0386x over previous
#include <cuda_runtime.h>
#include <cuda_bf16.h>
#include <cstdint>

#define BB 64
#define SS 512
#define EE 256
#define HH 512
#define FH 2048
#define NBLK 128
#define NT 256

// ---- recurrence smem byte offsets
#define WH 0                 // weight hi: 40 rows x 520 bf16 (pitch 1040B)
#define WL 41600
#define PH 83200             // state planes: 32 rows x 520 bf16 each
#define PHL 116480
#define PC 149760
#define PCL 183040
#define BIASB 216320         // 40 floats
#define RED 83200            // reduce scratch aliases PH (20480B)
#define SMEM_DYN 216480
#define PITCH 1040

// ---- u_gemm smem byte offsets (XH also aliased by OUT after mainloop)
#define UXH 0                // X hi: 64 rows x 528B
#define UXL 33792
#define UUH 67584            // U hi: 128 rows x 528B
#define UUL 135168
#define SMEM_UG 202752
#define UPITCH 528

__device__ __align__(16) __nv_bfloat16 g_hhi[BB * HH];
__device__ __align__(16) __nv_bfloat16 g_hlo[BB * HH];
__device__ __align__(16) __nv_bfloat16 g_chi[BB * HH];
__device__ __align__(16) __nv_bfloat16 g_clo[BB * HH];
__device__ float g_u[(size_t)SS * BB * FH];
// Two independent per-half barrier counters, 256B apart (different L2 lines).
// Monotonic, never reset (graph-replay safe).
__device__ unsigned g_cnt2[2 * 64];

// ---------------------------------------------------------------------------
__device__ __forceinline__ uint32_t smem_u32(const void* p) {
    uint32_t a;
    asm("{ .reg .u64 t; cvta.to.shared.u64 t, %1; cvt.u32.u64 %0, t; }"
        : "=r"(a) : "l"(p));
    return a;
}
__device__ __forceinline__ void cpasync16(uint32_t dst, const void* src) {
    asm volatile("cp.async.cg.shared.global [%0], [%1], 16;"
                 :: "r"(dst), "l"(src));
}
#define CP_COMMIT() asm volatile("cp.async.commit_group;")
#define CP_WAIT1()  asm volatile("cp.async.wait_group 1;")
#define CP_WAIT0()  asm volatile("cp.async.wait_group 0;")
__device__ __forceinline__ unsigned short f2bf(float x) {
    unsigned short r;
    asm("cvt.rn.bf16.f32 %0, %1;" : "=h"(r) : "f"(x));
    return r;
}
__device__ __forceinline__ float bf2f(unsigned short u) {
    return __uint_as_float(((unsigned)u) << 16);
}
__device__ __forceinline__ float tanha(float x) {
    float y;
    asm("tanh.approx.f32 %0, %1;" : "=f"(y) : "f"(x));
    return y;
}
__device__ __forceinline__ float sigm(float x) {
    return 0.5f * tanha(0.5f * x) + 0.5f;
}
#define LDM4(r, a) \
    asm volatile("ldmatrix.sync.aligned.m8n8.x4.shared.b16 {%0,%1,%2,%3},[%4];" \
        : "=r"((r)[0]), "=r"((r)[1]), "=r"((r)[2]), "=r"((r)[3]) : "r"(a))
#define LDM2(r0, r1, a) \
    asm volatile("ldmatrix.sync.aligned.m8n8.x2.shared.b16 {%0,%1},[%2];" \
        : "=r"(r0), "=r"(r1) : "r"(a))
#define MMA(d, a, b0, b1) \
    asm volatile("mma.sync.aligned.m16n8k16.row.col.f32.bf16.bf16.f32 " \
        "{%0,%1,%2,%3},{%4,%5,%6,%7},{%8,%9},{%0,%1,%2,%3};" \
        : "+f"((d)[0]), "+f"((d)[1]), "+f"((d)[2]), "+f"((d)[3]) \
        : "r"((a)[0]), "r"((a)[1]), "r"((a)[2]), "r"((a)[3]), "r"(b0), "r"(b1))

// Per-batch-half flat monotonic grid barrier: 64 arrivals each, independent
// counters on separate L2 lines (R16-measured best).
__device__ __forceinline__ void gridbar_half(int bh) {
    __syncthreads();
    if (threadIdx.x == 0) {
        __threadfence();
        unsigned* cnt = &g_cnt2[bh * 64];
        unsigned my = atomicAdd(cnt, 1u);
        unsigned target = (my / 64u + 1u) * 64u;
        unsigned v;
        do {
            asm volatile("ld.acquire.gpu.global.u32 %0, [%1];"
                         : "=r"(v) : "l"(cnt) : "memory");
        } while (v < target);
    }
    __syncthreads();
}

// ---------------------------------------------------------------------------
// u_all GEMM via split-bf16 mma.sync (3-pass). Block: 64 batches at fixed s
// x 128 n-cols, K=256 smem-resident. 8 warps = 2 m-halves x 4 n-quarters.
// ---------------------------------------------------------------------------
__global__ __launch_bounds__(256) void u_gemm_mma(
    const float* __restrict__ X, const float* __restrict__ U,
    const float* __restrict__ Ub)
{
    extern __shared__ char smc[];
    const uint32_t base = smem_u32(smc);
    const int t = threadIdx.x, wid = t >> 5, lane = t & 31;
    const int s = blockIdx.x, n0 = blockIdx.y * 128;
    const int mw = wid & 1, nw = wid >> 1;

    // load + split-convert X (64 x 256 fp32 -> hi/lo bf16 planes)
#pragma unroll
    for (int q = 0; q < 16; q++) {
        int i = t + 256 * q;
        int row = i >> 6, k4 = i & 63;
        float4 v = __ldg((const float4*)(X + ((size_t)row * SS + s) * EE) + k4);
        unsigned short h0 = f2bf(v.x), h1 = f2bf(v.y),
                       h2 = f2bf(v.z), h3 = f2bf(v.w);
        unsigned short l0 = f2bf(v.x - bf2f(h0)), l1 = f2bf(v.y - bf2f(h1)),
                       l2 = f2bf(v.z - bf2f(h2)), l3 = f2bf(v.w - bf2f(h3));
        uint2 hv = make_uint2((uint32_t)h0 | ((uint32_t)h1 << 16),
                              (uint32_t)h2 | ((uint32_t)h3 << 16));
        uint2 lv = make_uint2((uint32_t)l0 | ((uint32_t)l1 << 16),
                              (uint32_t)l2 | ((uint32_t)l3 << 16));
        *(uint2*)(smc + UXH + row * UPITCH + k4 * 8) = hv;
        *(uint2*)(smc + UXL + row * UPITCH + k4 * 8) = lv;
    }
    // load + split-convert U slice (128 x 256)
#pragma unroll
    for (int q = 0; q < 32; q++) {
        int i = t + 256 * q;
        int row = i >> 6, k4 = i & 63;
        float4 v = __ldg((const float4*)(U + (size_t)(n0 + row) * EE) + k4);
        unsigned short h0 = f2bf(v.x), h1 = f2bf(v.y),
                       h2 = f2bf(v.z), h3 = f2bf(v.w);
        unsigned short l0 = f2bf(v.x - bf2f(h0)), l1 = f2bf(v.y - bf2f(h1)),
                       l2 = f2bf(v.z - bf2f(h2)), l3 = f2bf(v.w - bf2f(h3));
        uint2 hv = make_uint2((uint32_t)h0 | ((uint32_t)h1 << 16),
                              (uint32_t)h2 | ((uint32_t)h3 << 16));
        uint2 lv = make_uint2((uint32_t)l0 | ((uint32_t)l1 << 16),
                              (uint32_t)l2 | ((uint32_t)l3 << 16));
        *(uint2*)(smc + UUH + row * UPITCH + k4 * 8) = hv;
        *(uint2*)(smc + UUL + row * UPITCH + k4 * 8) = lv;
    }
    __syncthreads();

    float acc[2][4][4];
#pragma unroll
    for (int mf = 0; mf < 2; mf++)
#pragma unroll
        for (int nf = 0; nf < 4; nf++)
#pragma unroll
            for (int r = 0; r < 4; r++) acc[mf][nf][r] = 0.f;

    const int l = lane & 15;
#pragma unroll
    for (int kt = 0; kt < 16; kt++) {
        uint32_t ah[2][4], al[2][4];
#pragma unroll
        for (int mf = 0; mf < 2; mf++) {
            uint32_t ad = base + UXH + (mw * 32 + mf * 16 + l) * UPITCH +
                          kt * 32 + (lane >> 4) * 16;
            LDM4(ah[mf], ad);
            LDM4(al[mf], ad + (UXL - UXH));
        }
        uint32_t bh_[4][2], bl_[4][2];
#pragma unroll
        for (int nf = 0; nf < 4; nf++) {
            uint32_t bd = base + UUH + (nw * 32 + nf * 8 + (l & 7)) * UPITCH +
                          kt * 32 + ((l >> 3) & 1) * 16;
            LDM2(bh_[nf][0], bh_[nf][1], bd);
            LDM2(bl_[nf][0], bl_[nf][1], bd + (UUL - UUH));
        }
#pragma unroll
        for (int mf = 0; mf < 2; mf++)
#pragma unroll
            for (int nf = 0; nf < 4; nf++) {
                MMA(acc[mf][nf], ah[mf], bh_[nf][0], bh_[nf][1]);
                MMA(acc[mf][nf], ah[mf], bl_[nf][0], bl_[nf][1]);
                MMA(acc[mf][nf], al[mf], bh_[nf][0], bh_[nf][1]);
            }
    }
    __syncthreads();   // OUT aliases XH region below

    // scatter frags to OUT (64 rows x 128 cols fp32, pitch 130 floats)
    float* OUT = (float*)smc;
#pragma unroll
    for (int mf = 0; mf < 2; mf++)
#pragma unroll
        for (int nf = 0; nf < 4; nf++)
#pragma unroll
            for (int r = 0; r < 4; r++) {
                int row = mw * 32 + mf * 16 + (lane >> 2) + (r >> 1) * 8;
                int col = nw * 32 + nf * 8 + (lane & 3) * 2 + (r & 1);
                OUT[row * 130 + col] = acc[mf][nf][r];
            }
    __syncthreads();

    // coalesced copy + bias
#pragma unroll
    for (int q = 0; q < 16; q++) {
        int i = t + 256 * q;
        int row = i >> 6, c2 = i & 63;
        float2 v = *(float2*)(OUT + row * 130 + c2 * 2);
        int n = n0 + c2 * 2;
        v.x += __ldg(Ub + n);
        v.y += __ldg(Ub + n + 1);
        *(float2*)(g_u + ((size_t)s * BB + row) * FH + n) = v;
    }
}

// ---------------------------------------------------------------------------
// Persistent mma.sync recurrence. 128 blocks = 64 j-tiles x 2 batch-halves.
// 8 warps = 2 m-tiles x 4 k-quarters. Staging split: h planes (group A) /
// c planes (group B); gate MMAs overlap the c-plane transfer.
// ---------------------------------------------------------------------------
__global__ __launch_bounds__(NT, 1) void lstm_mma(
    const float* __restrict__ Wall, const float* __restrict__ Wall_b,
    const float* __restrict__ Wd, const float* __restrict__ Wd_b,
    const float* __restrict__ ts, float* __restrict__ out, int write_tail)
{
    extern __shared__ char smc[];
    const uint32_t base = smem_u32(smc);
    const int t = threadIdx.x, wid = t >> 5, lane = t & 31;
    const int jt = blockIdx.x >> 1, bh = blockIdx.x & 1;
    const int j0 = jt * 8;
    const int mw = wid & 1, kq = wid >> 1;

    // one-time: split weights into smem (40 rows x 512, pitch 1040B)
#pragma unroll 4
    for (int it = 0; it < 80; it++) {
        int i = t + NT * it;
        int r = i >> 9, k = i & 511;
        float w = (r < 32) ? Wall[(size_t)((r >> 3) * HH + j0 + (r & 7)) * HH + k]
                           : Wd[(size_t)(j0 + (r & 7)) * HH + k];
        unsigned short hi = f2bf(w);
        unsigned short lo = f2bf(w - bf2f(hi));
        *(unsigned short*)(smc + WH + r * PITCH + k * 2) = hi;
        *(unsigned short*)(smc + WL + r * PITCH + k * 2) = lo;
    }
    if (t < 40) {
        ((float*)(smc + BIASB))[t] =
            (t < 32) ? Wall_b[(t >> 3) * HH + j0 + (t & 7)]
                     : Wd_b[j0 + (t & 7)];
    }
    __syncthreads();

    // persistent B-hi fragments: 5 slots x 8 k-tiles x 2 regs
    uint32_t bhi[5][8][2];
    {
        int l = lane & 15;
        int brow = l & 7, bk = (l >> 3) & 1;
#pragma unroll
        for (int ns = 0; ns < 5; ns++)
#pragma unroll
            for (int kt = 0; kt < 8; kt++) {
                uint32_t a = base + WH + (ns * 8 + brow) * PITCH +
                             (kq * 128 + kt * 16) * 2 + bk * 16;
                LDM2(bhi[ns][kt][0], bhi[ns][kt][1], a);
            }
    }
    const uint32_t bloAddr0 = base + WL + ((lane & 15) & 7) * PITCH +
                              (((lane & 15) >> 3) & 1) * 16 + kq * 256;
    const uint32_t aoff = (mw * 16 + (lane & 15)) * PITCH + (lane >> 4) * 16 +
                          kq * 256;

    // epilogue identity
    const int eb = t >> 3, ejl = t & 7;
    const int bg = bh * 32 + eb, ej = j0 + ejl;
    const float zb0 = ((float*)(smc + BIASB))[ejl];
    const float zb1 = ((float*)(smc + BIASB))[8 + ejl];
    const float zb2 = ((float*)(smc + BIASB))[16 + ejl];
    const float zb3 = ((float*)(smc + BIASB))[24 + ejl];
    const float zb4 = ((float*)(smc + BIASB))[32 + ejl];
    float ccar = 0.f;

    for (int s = 0; s < SS; s++) {
        // epilogue operand prefetch
        const float* ur = g_u + ((size_t)s * BB + bg) * FH + ej;
        float u0 = __ldcs(ur);
        float u1 = __ldcs(ur + HH);
        float u2 = __ldcs(ur + 2 * HH);
        float u3 = __ldcs(ur + 3 * HH);
        float tsv = __ldg(ts + (size_t)bg * SS + s);

        // stage state: h planes (group A), c planes (group B); s==0 zero-fill
        if (s == 0) {
#pragma unroll
            for (int q = 0; q < 33; q++) {
                int i = t + NT * q;
                if (i < 8320)
                    ((uint4*)(smc + PH))[i] = make_uint4(0, 0, 0, 0);
            }
        } else {
#pragma unroll
            for (int q = 0; q < 16; q++) {
                int i = t + NT * (q & 7);
                int row = i >> 6, seg = i & 63;
                int p = q >> 3;
                const __nv_bfloat16* gp = (p == 0) ? g_hhi : g_hlo;
                cpasync16(base + PH + p * 33280 + row * PITCH + seg * 16,
                          gp + (size_t)(bh * 32 + row) * HH + seg * 8);
            }
            CP_COMMIT();
#pragma unroll
            for (int q = 0; q < 16; q++) {
                int i = t + NT * (q & 7);
                int row = i >> 6, seg = i & 63;
                int p = q >> 3;
                const __nv_bfloat16* gp = (p == 0) ? g_chi : g_clo;
                cpasync16(base + PC + p * 33280 + row * PITCH + seg * 16,
                          gp + (size_t)(bh * 32 + row) * HH + seg * 8);
            }
            CP_COMMIT();
            CP_WAIT1();
        }
        __syncthreads();

        float acc[5][4];
#pragma unroll
        for (int ns = 0; ns < 5; ns++)
#pragma unroll
            for (int r = 0; r < 4; r++) acc[ns][r] = 0.f;

        // ---- gate MMAs (h planes) — overlap c-plane transfer
#pragma unroll
        for (int kt = 0; kt < 8; kt++) {
            uint32_t kb = kt * 32;
            uint32_t ahh[4], ahl[4];
            LDM4(ahh, base + PH + aoff + kb);
            LDM4(ahl, base + PHL + aoff + kb);
            uint32_t bl[4][2];
#pragma unroll
            for (int ns = 0; ns < 4; ns++)
                LDM2(bl[ns][0], bl[ns][1], bloAddr0 + ns * 8 * PITCH + kb);
#pragma unroll
            for (int ns = 0; ns < 4; ns++) {
                MMA(acc[ns], ahh, bhi[ns][kt][0], bhi[ns][kt][1]);
                MMA(acc[ns], ahh, bl[ns][0], bl[ns][1]);
                MMA(acc[ns], ahl, bhi[ns][kt][0], bhi[ns][kt][1]);
            }
        }
        if (s) CP_WAIT0();
        __syncthreads();

        // ---- decay MMAs (c planes)
#pragma unroll
        for (int kt = 0; kt < 8; kt++) {
            uint32_t kb = kt * 32;
            uint32_t ach[4], acl[4];
            LDM4(ach, base + PC + aoff + kb);
            LDM4(acl, base + PCL + aoff + kb);
            uint32_t bl0, bl1;
            LDM2(bl0, bl1, bloAddr0 + 4 * 8 * PITCH + kb);
            MMA(acc[4], ach, bhi[4][kt][0], bhi[4][kt][1]);
            MMA(acc[4], ach, bl0, bl1);
            MMA(acc[4], acl, bhi[4][kt][0], bhi[4][kt][1]);
        }
        __syncthreads();  // reduce scratch aliases PH plane

        // scatter partials: R[((kq*5+g)*32 + row)*8 + jl]
        {
            float* R = (float*)(smc + RED);
#pragma unroll
            for (int ns = 0; ns < 5; ns++)
#pragma unroll
                for (int r = 0; r < 4; r++) {
                    int row = mw * 16 + (lane >> 2) + (r >> 1) * 8;
                    int jl = (lane & 3) * 2 + (r & 1);
                    R[((kq * 5 + ns) * 32 + row) * 8 + jl] = acc[ns][r];
                }
        }
        __syncthreads();

        // gather + gate epilogue (each thread: one (batch, j))
        {
            const float* R = (float*)(smc + RED);
            float s0 = 0, s1 = 0, s2 = 0, s3 = 0, s4 = 0;
#pragma unroll
            for (int k2 = 0; k2 < 4; k2++) {
                const float* Rq = R + (k2 * 5 * 32 + eb) * 8 + ejl;
                s0 += Rq[0];
                s1 += Rq[32 * 8];
                s2 += Rq[64 * 8];
                s3 += Rq[96 * 8];
                s4 += Rq[128 * 8];
            }
            float pf = s0 + zb0 + u0;
            float pi = s1 + zb1 + u1;
            float po = s2 + zb2 + u2;
            float pg = s3 + zb3 + u3;
            float dd = s4 + zb4;

            float cs1 = tanha(dd);
            float cadj = (ccar - cs1) + cs1 * tsv;
            float cnew = sigm(pf) * cadj + sigm(pi) * sigm(pg);
            float hnew = sigm(po) * tanha(cnew);
            ccar = cnew;

            // state planes FIRST (next step's critical data), then out
            unsigned short hh = f2bf(hnew);
            unsigned short hl = f2bf(hnew - bf2f(hh));
            unsigned short ch = f2bf(cnew);
            unsigned short cl = f2bf(cnew - bf2f(ch));
            size_t po_ = (size_t)bg * HH + ej;
            g_hhi[po_] = *(__nv_bfloat16*)&hh;
            g_hlo[po_] = *(__nv_bfloat16*)&hl;
            g_chi[po_] = *(__nv_bfloat16*)&ch;
            g_clo[po_] = *(__nv_bfloat16*)&cl;

            out[((size_t)bg * SS + s) * HH + ej] = hnew;

            if (s == SS - 1 && write_tail) {
                out[(size_t)BB * SS * HH + po_] = hnew;
                out[(size_t)BB * SS * HH + (size_t)BB * HH + po_] = cnew;
            }
        }

        if (s != SS - 1) gridbar_half(bh);
    }
}

// ---------------------------------------------------------------------------
extern "C" void kernel_launch(void* const* d_in, const int* in_sizes, int n_in,
                              void* d_out, int out_size) {
    const float* X      = (const float*)d_in[0];
    const float* ts     = (const float*)d_in[1];
    const float* Wall   = (const float*)d_in[2];
    const float* Wall_b = (const float*)d_in[3];
    const float* U      = (const float*)d_in[4];
    const float* Ub     = (const float*)d_in[5];
    const float* Wd     = (const float*)d_in[6];
    const float* Wdb    = (const float*)d_in[7];
    float* out = (float*)d_out;

    cudaFuncSetAttribute(u_gemm_mma, cudaFuncAttributeMaxDynamicSharedMemorySize,
                         SMEM_UG);
    cudaFuncSetAttribute(lstm_mma, cudaFuncAttributeMaxDynamicSharedMemorySize,
                         SMEM_DYN);

    dim3 gu(SS, 16);
    u_gemm_mma<<<gu, 256, SMEM_UG>>>(X, U, Ub);

    long long need = (long long)BB * SS * HH + 2LL * BB * HH;
    int write_tail = ((long long)out_size >= need) ? 1 : 0;
    lstm_mma<<<NBLK, NT, SMEM_DYN>>>(Wall, Wall_b, Wd, Wdb, ts, out, write_tail);
}